// round 10
// baseline (speedup 1.0000x reference)
#include <cuda_runtime.h>
#include <cfloat>
#include <math.h>
#include <cstdio>

// Edge lists for the two MSTs (max n = 4096 -> 4095 edges each).
#define NMAX 4096
__device__ int2 g_edges[2][NMAX];

// Phase timing (cycles, tid0 of each block): [redux, bar, combine, mem+relax, total]
__device__ unsigned long long g_phase[2][5];

// ---------------------------------------------------------------------------
// Pre-kernel: pull both matrices into L2 (~126 MB L2 vs 128 MB data).
// Measured: ~13 us @ 5.9 TB/s.
// ---------------------------------------------------------------------------
__global__ void prefetch_kernel(const float* __restrict__ d1,
                                const float* __restrict__ d2,
                                int n)
{
    const size_t total = (size_t)n * n;
    const int nb = gridDim.x >> 1;
    const float* __restrict__ m = (blockIdx.x < nb) ? d1 : d2;
    const int b = blockIdx.x % nb;

    const size_t chunk = (total + nb - 1) / nb;
    const size_t start = (size_t)b * chunk;
    const size_t end   = (start + chunk < total) ? start + chunk : total;

    for (size_t off = start + (size_t)threadIdx.x * 32;
         off < end;
         off += (size_t)blockDim.x * 32) {
        asm volatile("prefetch.global.L2 [%0];" :: "l"(m + off));
    }
}

// ---------------------------------------------------------------------------
// Prim's MST, bit-exact vs reference (strict-< relax, FLT_MAX masking,
// argmin tie-break to lowest index). One block per matrix, 256 threads
// (8 warps), 16 owned elements per thread. All register-array indexing is
// compile-time (fully unrolled / predicated) -> no local-memory spills.
// Single __syncthreads per iteration via double-buffered per-warp bests.
// Phase-instrumented with clock64 (tid0 only stores).
// ---------------------------------------------------------------------------
__global__ __launch_bounds__(256, 1)
void mst_kernel(const float* __restrict__ d1,
                const float* __restrict__ d2,
                int n)
{
    const float* __restrict__ d = (blockIdx.x == 0) ? d1 : d2;
    int2* edges = g_edges[blockIdx.x];

    const int tid  = threadIdx.x;
    const int lane = tid & 31;
    const int wid  = tid >> 5;
    const int base = tid << 4;            // first of 16 owned indices

    __shared__ unsigned long long wbest[2][8];

    // ---- init: min_dist = d[0,:], parent = 0, node 0 in tree ----
    float md[16];
    int   par[16];
    {
        const float4* r0 = reinterpret_cast<const float4*>(d) + tid * 4;
        #pragma unroll
        for (int q = 0; q < 4; ++q) {
            float4 a = r0[q];
            md[q * 4 + 0] = a.x; md[q * 4 + 1] = a.y;
            md[q * 4 + 2] = a.z; md[q * 4 + 3] = a.w;
        }
    }
    #pragma unroll
    for (int k = 0; k < 16; ++k) par[k] = 0;
    if (tid == 0) md[0] = FLT_MAX;        // node 0 already in tree

    // packed key: (float bits << 32) | index  — min() => lowest value,
    // then lowest index (== jnp.argmin tie-break), bits order-preserving >=0.
    #define PKEY(K) ((((unsigned long long)__float_as_uint(md[K])) << 32) \
                     | (unsigned)(base + (K)))

    unsigned long long lkey;
    {
        unsigned long long t[8];
        #pragma unroll
        for (int k = 0; k < 8; ++k) t[k] = min(PKEY(2*k), PKEY(2*k+1));
        t[0] = min(t[0], t[1]); t[2] = min(t[2], t[3]);
        t[4] = min(t[4], t[5]); t[6] = min(t[6], t[7]);
        lkey = min(min(t[0], t[2]), min(t[4], t[6]));
    }

    unsigned long long c_red = 0, c_bar = 0, c_comb = 0, c_mem = 0;
    const unsigned long long t_start = clock64();

    int buf = 0;
    for (int it = 0; it < n - 1; ++it) {
        const unsigned long long t0 = clock64();

        // ---- warp argmin: two dependent 32-bit hardware reductions ----
        const unsigned lv   = (unsigned)(lkey >> 32);
        const unsigned vmin = __reduce_min_sync(0xffffffffu, lv);
        const unsigned cand = (lv == vmin) ? (unsigned)lkey : 0xFFFFFFFFu;
        const unsigned imin = __reduce_min_sync(0xffffffffu, cand);
        if (lane == 0)
            wbest[buf][wid] = (((unsigned long long)vmin) << 32) | imin;

        const unsigned long long t1 = clock64();
        __syncthreads();
        const unsigned long long t2 = clock64();

        // ---- block argmin: every thread tree-mins the 8 broadcast entries ----
        const unsigned long long* wb = wbest[buf];
        unsigned long long a0 = min(wb[0], wb[1]);
        unsigned long long a1 = min(wb[2], wb[3]);
        unsigned long long a2 = min(wb[4], wb[5]);
        unsigned long long a3 = min(wb[6], wb[7]);
        const unsigned long long bb = min(min(a0, a1), min(a2, a3));
        const int j = (int)(unsigned)bb;

        const unsigned long long t3 = clock64();

        // ---- row load ASAP (L2-resident after prefetch; evict-first:
        //      each row is dead after consumption) ----
        const float4* rp =
            reinterpret_cast<const float4*>(d + (size_t)j * n) + tid * 4;
        const float4 v0 = __ldcs(rp + 0);
        const float4 v1 = __ldcs(rp + 1);
        const float4 v2 = __ldcs(rp + 2);
        const float4 v3 = __ldcs(rp + 3);

        // ---- owner records edge (parent BEFORE relax), marks j in-tree.
        //      Static indices only -> stays in registers. ----
        if ((j >> 4) == tid) {
            const int jj = j & 15;
            #pragma unroll
            for (int k = 0; k < 16; ++k) {
                if (jj == k) {
                    edges[it] = make_int2(par[k], j);
                    md[k] = FLT_MAX;
                }
            }
        }

        // ---- relax (strict <, skip in-tree) fused with local argmin ----
        const float v[16] = { v0.x, v0.y, v0.z, v0.w,
                              v1.x, v1.y, v1.z, v1.w,
                              v2.x, v2.y, v2.z, v2.w,
                              v3.x, v3.y, v3.z, v3.w };
        #pragma unroll
        for (int k = 0; k < 16; ++k) {
            if (md[k] != FLT_MAX && v[k] < md[k]) {
                md[k]  = v[k];
                par[k] = j;
            }
        }
        {
            unsigned long long t[8];
            #pragma unroll
            for (int k = 0; k < 8; ++k) t[k] = min(PKEY(2*k), PKEY(2*k+1));
            t[0] = min(t[0], t[1]); t[2] = min(t[2], t[3]);
            t[4] = min(t[4], t[5]); t[6] = min(t[6], t[7]);
            lkey = min(min(t[0], t[2]), min(t[4], t[6]));
        }

        const unsigned long long t4 = clock64();
        c_red  += t1 - t0;
        c_bar  += t2 - t1;
        c_comb += t3 - t2;
        c_mem  += t4 - t3;

        buf ^= 1;
    }
    #undef PKEY

    if (tid == 0) {
        g_phase[blockIdx.x][0] = c_red;
        g_phase[blockIdx.x][1] = c_bar;
        g_phase[blockIdx.x][2] = c_comb;
        g_phase[blockIdx.x][3] = c_mem;
        g_phase[blockIdx.x][4] = clock64() - t_start;
    }
}

// ---------------------------------------------------------------------------
// Gather both signatures, reduce, and report phase timings (diagnostic).
// ---------------------------------------------------------------------------
__global__ __launch_bounds__(1024, 1)
void finalize_kernel(const float* __restrict__ d1,
                     const float* __restrict__ d2,
                     float* __restrict__ out,
                     int n)
{
    __shared__ float warp_sums[32];
    const int tid = threadIdx.x;

    float acc = 0.0f;
    for (int i = tid; i < n - 1; i += blockDim.x) {
        int2 e1 = g_edges[0][i];
        int2 e2 = g_edges[1][i];
        size_t o1 = (size_t)e1.x * n + e1.y;
        size_t o2 = (size_t)e2.x * n + e2.y;
        float a = d1[o1] - d2[o1];
        float b = d1[o2] - d2[o2];
        acc += a * a + b * b;
    }
    #pragma unroll
    for (int o = 16; o; o >>= 1)
        acc += __shfl_xor_sync(0xffffffffu, acc, o);
    if ((tid & 31) == 0) warp_sums[tid >> 5] = acc;
    __syncthreads();
    if (tid < 32) {
        float v = (tid < (int)(blockDim.x >> 5)) ? warp_sums[tid] : 0.0f;
        #pragma unroll
        for (int o = 16; o; o >>= 1)
            v += __shfl_xor_sync(0xffffffffu, v, o);
        if (tid == 0) out[0] = v;
    }

    if (tid == 0) {
        printf("PHASES blk0 red=%llu bar=%llu comb=%llu mem=%llu tot=%llu | "
               "blk1 red=%llu bar=%llu comb=%llu mem=%llu tot=%llu\n",
               g_phase[0][0], g_phase[0][1], g_phase[0][2], g_phase[0][3],
               g_phase[0][4],
               g_phase[1][0], g_phase[1][1], g_phase[1][2], g_phase[1][3],
               g_phase[1][4]);
    }
}

extern "C" void kernel_launch(void* const* d_in, const int* in_sizes, int n_in,
                              void* d_out, int out_size)
{
    const float* d1 = (const float*)d_in[0];
    const float* d2 = (const float*)d_in[1];
    float* out = (float*)d_out;

    const int n = (int)lrint(sqrt((double)in_sizes[0]));   // 4096

    prefetch_kernel<<<64, 1024>>>(d1, d2, n);
    mst_kernel<<<2, 256>>>(d1, d2, n);
    finalize_kernel<<<1, 1024>>>(d1, d2, out, n);
}